// round 1
// baseline (speedup 1.0000x reference)
#include <cuda_runtime.h>

// Deterministic two-pass reduction:
//   pass 1: grid-stride float4 dot-product partials -> g_partials[block]
//   pass 2: single block reduces g_partials, writes -sum/B to d_out[0]

#define NBLOCKS 2048
#define NTHREADS 256

__device__ float g_partials[NBLOCKS];

__global__ __launch_bounds__(NTHREADS) void dot_partial_kernel(
    const float4* __restrict__ fs, const float4* __restrict__ ft, int n4) {
    float acc = 0.0f;
    int i = blockIdx.x * NTHREADS + threadIdx.x;
    const int stride = NBLOCKS * NTHREADS;

    // Unroll by 4 to front-batch loads (MLP for the L1tex queue)
    #pragma unroll 1
    for (; i + 3 * stride < n4; i += 4 * stride) {
        float4 a0 = fs[i];
        float4 a1 = fs[i + stride];
        float4 a2 = fs[i + 2 * stride];
        float4 a3 = fs[i + 3 * stride];
        float4 b0 = ft[i];
        float4 b1 = ft[i + stride];
        float4 b2 = ft[i + 2 * stride];
        float4 b3 = ft[i + 3 * stride];
        acc = fmaf(a0.x, b0.x, acc); acc = fmaf(a0.y, b0.y, acc);
        acc = fmaf(a0.z, b0.z, acc); acc = fmaf(a0.w, b0.w, acc);
        acc = fmaf(a1.x, b1.x, acc); acc = fmaf(a1.y, b1.y, acc);
        acc = fmaf(a1.z, b1.z, acc); acc = fmaf(a1.w, b1.w, acc);
        acc = fmaf(a2.x, b2.x, acc); acc = fmaf(a2.y, b2.y, acc);
        acc = fmaf(a2.z, b2.z, acc); acc = fmaf(a2.w, b2.w, acc);
        acc = fmaf(a3.x, b3.x, acc); acc = fmaf(a3.y, b3.y, acc);
        acc = fmaf(a3.z, b3.z, acc); acc = fmaf(a3.w, b3.w, acc);
    }
    for (; i < n4; i += stride) {
        float4 a = fs[i];
        float4 b = ft[i];
        acc = fmaf(a.x, b.x, acc); acc = fmaf(a.y, b.y, acc);
        acc = fmaf(a.z, b.z, acc); acc = fmaf(a.w, b.w, acc);
    }

    // warp reduce
    #pragma unroll
    for (int off = 16; off > 0; off >>= 1)
        acc += __shfl_xor_sync(0xFFFFFFFFu, acc, off);

    __shared__ float s[NTHREADS / 32];
    int lane = threadIdx.x & 31;
    int wid = threadIdx.x >> 5;
    if (lane == 0) s[wid] = acc;
    __syncthreads();

    if (wid == 0) {
        float v = (lane < NTHREADS / 32) ? s[lane] : 0.0f;
        #pragma unroll
        for (int off = 4; off > 0; off >>= 1)
            v += __shfl_xor_sync(0xFFFFFFFFu, v, off);
        if (lane == 0) g_partials[blockIdx.x] = v;
    }
}

__global__ __launch_bounds__(1024) void finalize_kernel(float* __restrict__ out,
                                                       float neg_inv_b) {
    float acc = 0.0f;
    for (int i = threadIdx.x; i < NBLOCKS; i += 1024)
        acc += g_partials[i];

    #pragma unroll
    for (int off = 16; off > 0; off >>= 1)
        acc += __shfl_xor_sync(0xFFFFFFFFu, acc, off);

    __shared__ float s[32];
    int lane = threadIdx.x & 31;
    int wid = threadIdx.x >> 5;
    if (lane == 0) s[wid] = acc;
    __syncthreads();

    if (wid == 0) {
        float v = (lane < 32) ? s[lane] : 0.0f;
        #pragma unroll
        for (int off = 16; off > 0; off >>= 1)
            v += __shfl_xor_sync(0xFFFFFFFFu, v, off);
        if (lane == 0) out[0] = v * neg_inv_b;
    }
}

extern "C" void kernel_launch(void* const* d_in, const int* in_sizes, int n_in,
                              void* d_out, int out_size) {
    const float4* fs = (const float4*)d_in[0];
    const float4* ft = (const float4*)d_in[1];
    float* out = (float*)d_out;

    int n = in_sizes[0];       // 65536 * 512 = 33554432 floats
    int n4 = n >> 2;           // float4 count

    float neg_inv_b = -1.0f / 65536.0f;  // B = 65536 (n / D with D = 512)
    // Derive B generically in case of shape variants: B = n / 512
    {
        int B = n / 512;
        neg_inv_b = -1.0f / (float)B;
    }

    dot_partial_kernel<<<NBLOCKS, NTHREADS>>>(fs, ft, n4);
    finalize_kernel<<<1, 1024>>>(out, neg_inv_b);
}